// round 14
// baseline (speedup 1.0000x reference)
#include <cuda_runtime.h>
#include <cuda_bf16.h>
#include <cstdint>
#include <cstddef>

// ---------------------------------------------------------------------------
// Problem constants
// ---------------------------------------------------------------------------
#define NB    4
#define NSEQ  2048
#define DIMM  512
#define NH    8
#define DHEAD 64
#define QKVC  1536   // 3 * inner

// Scratch: all intermediates live as bf16 hi/lo residual planes.
__device__ __nv_bfloat16 g_xh [(size_t)NB * NSEQ * DIMM];
__device__ __nv_bfloat16 g_xl [(size_t)NB * NSEQ * DIMM];
__device__ __nv_bfloat16 g_qkvh[(size_t)NB * NSEQ * QKVC];   // q third pre-scaled by 1/8
__device__ __nv_bfloat16 g_qkvl[(size_t)NB * NSEQ * QKVC];
__device__ __nv_bfloat16 g_aoh[(size_t)NB * NSEQ * DIMM];
__device__ __nv_bfloat16 g_aol[(size_t)NB * NSEQ * DIMM];
__device__ __nv_bfloat16 g_wqkvT_hi[(size_t)QKVC * DIMM];
__device__ __nv_bfloat16 g_wqkvT_lo[(size_t)QKVC * DIMM];
__device__ __nv_bfloat16 g_woutT_hi[(size_t)DIMM * DIMM];
__device__ __nv_bfloat16 g_woutT_lo[(size_t)DIMM * DIMM];

// ---------------------------------------------------------------------------
// Helpers
// ---------------------------------------------------------------------------
__device__ __forceinline__ void split_pack(float a, float b, uint32_t& hi, uint32_t& lo) {
    __nv_bfloat162 h = __floats2bfloat162_rn(a, b);
    float ra = a - __bfloat162float(h.x);
    float rb = b - __bfloat162float(h.y);
    __nv_bfloat162 l = __floats2bfloat162_rn(ra, rb);
    hi = reinterpret_cast<uint32_t&>(h);
    lo = reinterpret_cast<uint32_t&>(l);
}

__device__ __forceinline__ void mma16(float* c, const uint32_t* a, const uint32_t* b) {
    asm volatile(
        "mma.sync.aligned.m16n8k16.row.col.f32.bf16.bf16.f32 "
        "{%0,%1,%2,%3}, {%4,%5,%6,%7}, {%8,%9}, {%0,%1,%2,%3};\n"
        : "+f"(c[0]), "+f"(c[1]), "+f"(c[2]), "+f"(c[3])
        : "r"(a[0]), "r"(a[1]), "r"(a[2]), "r"(a[3]), "r"(b[0]), "r"(b[1]));
}

// ldmatrix x4, A-style tile order
__device__ __forceinline__ void ldsmA(uint32_t* f, uint32_t base, int strideB) {
    const int lane = threadIdx.x & 31;
    uint32_t a = base + (uint32_t)((((lane >> 3) & 1) * 8 + (lane & 7)) * strideB + (lane >> 4) * 16);
    asm volatile("ldmatrix.sync.aligned.m8n8.x4.shared.b16 {%0,%1,%2,%3}, [%4];"
                 : "=r"(f[0]), "=r"(f[1]), "=r"(f[2]), "=r"(f[3]) : "r"(a));
}
__device__ __forceinline__ void ldsmAT(uint32_t* f, uint32_t base, int strideB) {
    const int lane = threadIdx.x & 31;
    uint32_t a = base + (uint32_t)((((lane >> 3) & 1) * 8 + (lane & 7)) * strideB + (lane >> 4) * 16);
    asm volatile("ldmatrix.sync.aligned.m8n8.x4.trans.shared.b16 {%0,%1,%2,%3}, [%4];"
                 : "=r"(f[0]), "=r"(f[1]), "=r"(f[2]), "=r"(f[3]) : "r"(a));
}
__device__ __forceinline__ void ldsmB(uint32_t* f, uint32_t base, int strideB) {
    const int lane = threadIdx.x & 31;
    uint32_t a = base + (uint32_t)(((lane >> 4) * 8 + (lane & 7)) * strideB + ((lane >> 3) & 1) * 16);
    asm volatile("ldmatrix.sync.aligned.m8n8.x4.shared.b16 {%0,%1,%2,%3}, [%4];"
                 : "=r"(f[0]), "=r"(f[1]), "=r"(f[2]), "=r"(f[3]) : "r"(a));
}

// cp.async 16B
__device__ __forceinline__ void cpa16(uint32_t dst, const void* src) {
    asm volatile("cp.async.cg.shared.global [%0], [%1], 16;" :: "r"(dst), "l"(src));
}
#define CPA_COMMIT() asm volatile("cp.async.commit_group;" ::: "memory")
#define CPA_WAIT0()  asm volatile("cp.async.wait_group 0;" ::: "memory")
#define CPA_WAIT2()  asm volatile("cp.async.wait_group 2;" ::: "memory")

// ---------------------------------------------------------------------------
// Pre-passes
// ---------------------------------------------------------------------------
__global__ void split_f32(const float* __restrict__ in,
                          __nv_bfloat16* __restrict__ oh,
                          __nv_bfloat16* __restrict__ ol, int n2)
{
    int i = blockIdx.x * blockDim.x + threadIdx.x;
    if (i < n2) {
        float2 v = ((const float2*)in)[i];
        uint32_t h, l;
        split_pack(v.x, v.y, h, l);
        ((uint32_t*)oh)[i] = h;
        ((uint32_t*)ol)[i] = l;
    }
}

__global__ void transpose_split(const float* __restrict__ W,
                                __nv_bfloat16* __restrict__ Thi,
                                __nv_bfloat16* __restrict__ Tlo, int K, int N)
{
    __shared__ float t[32][33];
    const int n0 = blockIdx.x * 32, k0 = blockIdx.y * 32;
    const int tx = threadIdx.x, ty = threadIdx.y;
#pragma unroll
    for (int j = ty; j < 32; j += 8)
        t[j][tx] = W[(size_t)(k0 + j) * N + n0 + tx];
    __syncthreads();
#pragma unroll
    for (int j = ty; j < 32; j += 8) {
        float v = t[tx][j];
        __nv_bfloat16 h = __float2bfloat16(v);
        Thi[(size_t)(n0 + j) * K + k0 + tx] = h;
        Tlo[(size_t)(n0 + j) * K + k0 + tx] = __float2bfloat16(v - __bfloat162float(h));
    }
}

// ---------------------------------------------------------------------------
// bf16x3 GEMM: 2-stage ring, 80KB smem, <=128 regs -> 2 CTAs/SM.
// A-fragments software-pipelined (prefetch i+1 during i's mma stream);
// mma order j-interleaved so 4 independent accs sit between same-acc reuse.
// ---------------------------------------------------------------------------
#define GP 40
#define GPLANE (128 * GP)
#define GBUF (4 * GPLANE)     // Ahi, Alo, Bhi, Blo per stage

template <bool SPLITOUT>
__global__ __launch_bounds__(256, 2)
void gemm_cp(const __nv_bfloat16* __restrict__ Ah, const __nv_bfloat16* __restrict__ Al,
             const __nv_bfloat16* __restrict__ Bh, const __nv_bfloat16* __restrict__ Bl,
             const float* __restrict__ bias, float* __restrict__ Cf,
             __nv_bfloat16* __restrict__ Ch, __nv_bfloat16* __restrict__ Cl,
             int M, int N, int K)
{
    extern __shared__ __nv_bfloat16 smg[];
    const int tid = threadIdx.x;
    const int wid = tid >> 5, lane = tid & 31;
    const int gid = lane >> 2, tig = lane & 3;
    const int wm = wid >> 2, wn = wid & 3;
    const int m0 = blockIdx.y * 128, n0 = blockIdx.x * 128;
    const int NC = K >> 5;

    const uint32_t smg_u = (uint32_t)__cvta_generic_to_shared(smg);

    auto issue = [&](int c, int bb) {
        const uint32_t dbase = smg_u + (uint32_t)(bb * GBUF) * 2;
        const int kc = c * 32;
#pragma unroll
        for (int k = 0; k < 8; ++k) {
            const int i = tid + k * 256;        // 4 planes x 128 rows x 4 chunks
            const int plane = i >> 9;
            const int row = (i & 511) >> 2;
            const int ch = i & 3;
            const __nv_bfloat16* sp =
                plane == 0 ? (Ah + (size_t)(m0 + row) * K) :
                plane == 1 ? (Al + (size_t)(m0 + row) * K) :
                plane == 2 ? (Bh + (size_t)(n0 + row) * K) :
                             (Bl + (size_t)(n0 + row) * K);
            const uint32_t dst = dbase + (uint32_t)(plane * GPLANE * 2 + row * GP * 2 + ch * 16);
            cpa16(dst, sp + kc + ch * 8);
        }
        CPA_COMMIT();
    };

    float acc[4][4][4] = {};

    issue(0, 0);
    CPA_WAIT0();
    __syncthreads();

    for (int c = 0; c < NC; ++c) {
        if (c + 1 < NC) issue(c + 1, (c + 1) & 1);
        const uint32_t bu = smg_u + (uint32_t)((c & 1) * GBUF) * 2;
        const uint32_t Ahi_u = bu, Alo_u = bu + GPLANE * 2;
        const uint32_t Bhi_u = bu + 2 * GPLANE * 2, Blo_u = bu + 3 * GPLANE * 2;
#pragma unroll
        for (int ks = 0; ks < 2; ++ks) {
            // B fragments for this ks
            uint32_t bh2[4][2], bl2[4][2];
#pragma unroll
            for (int nb = 0; nb < 2; ++nb) {
                const uint32_t ro = (uint32_t)(((wn * 32 + nb * 16) * GP + ks * 16) * 2);
                uint32_t t[4];
                ldsmB(t, Bhi_u + ro, GP * 2);
                bh2[nb * 2][0] = t[0]; bh2[nb * 2][1] = t[1];
                bh2[nb * 2 + 1][0] = t[2]; bh2[nb * 2 + 1][1] = t[3];
                ldsmB(t, Blo_u + ro, GP * 2);
                bl2[nb * 2][0] = t[0]; bl2[nb * 2][1] = t[1];
                bl2[nb * 2 + 1][0] = t[2]; bl2[nb * 2 + 1][1] = t[3];
            }
            // A fragments: double-buffered in registers, prefetch i+1
            uint32_t ah[2][4], al[2][4];
            {
                const uint32_t ro = (uint32_t)(((wm * 64) * GP + ks * 16) * 2);
                ldsmA(ah[0], Ahi_u + ro, GP * 2);
                ldsmA(al[0], Alo_u + ro, GP * 2);
            }
#pragma unroll
            for (int i = 0; i < 4; ++i) {
                const int cur = i & 1, nxt = cur ^ 1;
                if (i < 3) {
                    const uint32_t ro = (uint32_t)(((wm * 64 + (i + 1) * 16) * GP + ks * 16) * 2);
                    ldsmA(ah[nxt], Ahi_u + ro, GP * 2);
                    ldsmA(al[nxt], Alo_u + ro, GP * 2);
                }
                // j-interleaved: per-acc order unchanged (hi.hi, hi.lo, lo.hi)
#pragma unroll
                for (int j = 0; j < 4; ++j) mma16(acc[i][j], ah[cur], bh2[j]);
#pragma unroll
                for (int j = 0; j < 4; ++j) mma16(acc[i][j], ah[cur], bl2[j]);
#pragma unroll
                for (int j = 0; j < 4; ++j) mma16(acc[i][j], al[cur], bh2[j]);
            }
        }
        if (c + 1 < NC) { CPA_WAIT0(); __syncthreads(); }
    }

    // epilogue
    const float qs = (SPLITOUT && n0 < DIMM) ? 0.125f : 1.0f;
#pragma unroll
    for (int i = 0; i < 4; ++i) {
        const int r0 = m0 + wm * 64 + i * 16 + gid;
#pragma unroll
        for (int j = 0; j < 4; ++j) {
            const int col = n0 + wn * 32 + j * 8 + tig * 2;
            if (SPLITOUT) {
                uint32_t h, l;
                split_pack(acc[i][j][0] * qs, acc[i][j][1] * qs, h, l);
                *(uint32_t*)(Ch + (size_t)r0 * N + col) = h;
                *(uint32_t*)(Cl + (size_t)r0 * N + col) = l;
                split_pack(acc[i][j][2] * qs, acc[i][j][3] * qs, h, l);
                *(uint32_t*)(Ch + (size_t)(r0 + 8) * N + col) = h;
                *(uint32_t*)(Cl + (size_t)(r0 + 8) * N + col) = l;
            } else {
                const float bx = bias[col], by = bias[col + 1];
                *(float2*)(Cf + (size_t)r0 * N + col) = make_float2(acc[i][j][0] + bx, acc[i][j][1] + by);
                *(float2*)(Cf + (size_t)(r0 + 8) * N + col) = make_float2(acc[i][j][2] + bx, acc[i][j][3] + by);
            }
        }
    }
}

// ---------------------------------------------------------------------------
// Flash attention: bf16x3, 4-stage cp.async KV ring, P frags in registers.
// mma streams j-interleaved (independent acc chains); otherwise round-13.
// ---------------------------------------------------------------------------
#define AP 72
#define APLANE_Q (128 * AP)
#define APLANE_K (64 * AP)
#define KVBUF (4 * APLANE_K)

__global__ __launch_bounds__(256)
void attn_cp(const __nv_bfloat16* __restrict__ qh_g, const __nv_bfloat16* __restrict__ ql_g,
             __nv_bfloat16* __restrict__ aoh, __nv_bfloat16* __restrict__ aol)
{
    extern __shared__ __nv_bfloat16 smb[];
    __nv_bfloat16* QPh = smb;
    __nv_bfloat16* QPl = QPh + APLANE_Q;
    __nv_bfloat16* KV  = QPl + APLANE_Q;    // [4][4 planes][64][AP]

    const uint32_t QPh_u = (uint32_t)__cvta_generic_to_shared(QPh);
    const uint32_t QPl_u = (uint32_t)__cvta_generic_to_shared(QPl);
    const uint32_t KV_u  = (uint32_t)__cvta_generic_to_shared(KV);

    const int qt = blockIdx.x, h = blockIdx.y, b = blockIdx.z;
    const int tid = threadIdx.x;
    const int wid = tid >> 5, lane = tid & 31;
    const int gid = lane >> 2, tig = lane & 3;
    const int w16 = wid * 16;

    auto issueQ = [&] {
        const size_t qbase = ((size_t)b * NSEQ + (size_t)qt * 128) * QKVC + h * DHEAD;
#pragma unroll
        for (int k = 0; k < 8; ++k) {
            const int i = tid + k * 256;
            const int plane = i >> 10;
            const int row = (i & 1023) >> 3;
            const int ch = i & 7;
            const __nv_bfloat16* src = (plane ? ql_g : qh_g) + qbase + (size_t)row * QKVC + ch * 8;
            const uint32_t dst = (plane ? QPl_u : QPh_u) + (uint32_t)(row * AP * 2 + ch * 16);
            cpa16(dst, src);
        }
        CPA_COMMIT();
    };
    auto issueKV = [&](int jt, int bb) {
        const size_t kbase = ((size_t)b * NSEQ + (size_t)jt * 64) * QKVC + h * DHEAD;
        const uint32_t dbase = KV_u + (uint32_t)(bb * KVBUF) * 2;
#pragma unroll
        for (int k = 0; k < 8; ++k) {
            const int i = tid + k * 256;
            const int plane = i >> 9;
            const int row = (i & 511) >> 3;
            const int ch = i & 7;
            const __nv_bfloat16* sp =
                plane == 0 ? (qh_g + kbase + DIMM) :
                plane == 1 ? (ql_g + kbase + DIMM) :
                plane == 2 ? (qh_g + kbase + 2 * DIMM) :
                             (ql_g + kbase + 2 * DIMM);
            const uint32_t dst = dbase + (uint32_t)(plane * APLANE_K * 2 + row * AP * 2 + ch * 16);
            cpa16(dst, sp + (size_t)row * QKVC + ch * 8);
        }
        CPA_COMMIT();
    };

    issueQ();
    issueKV(0, 0);
    issueKV(1, 1);
    issueKV(2, 2);

    uint32_t qh[4][4], ql[4][4];
    float m0 = -1e30f, m1 = -1e30f, l0 = 0.f, l1 = 0.f;
    float O[8][4] = {};

    const int NT = NSEQ / 64;
    for (int jt = 0; jt < NT; ++jt) {
        CPA_WAIT2();
        __syncthreads();
        if (jt == 0) {
#pragma unroll
            for (int ks = 0; ks < 4; ++ks) {
                const uint32_t ro = (uint32_t)((w16 * AP + ks * 16) * 2);
                ldsmA(qh[ks], QPh_u + ro, AP * 2);
                ldsmA(ql[ks], QPl_u + ro, AP * 2);
            }
        }
        if (jt + 3 < NT) issueKV(jt + 3, (jt + 3) & 3);

        const uint32_t bu = KV_u + (uint32_t)((jt & 3) * KVBUF) * 2;
        const uint32_t Kh_u = bu, Kl_u = bu + APLANE_K * 2;
        const uint32_t Vh_u = bu + 2 * APLANE_K * 2, Vl_u = bu + 3 * APLANE_K * 2;

        // S = Q @ K^T (1/8 scale folded into Q)
        float s[8][4];
#pragma unroll
        for (int j = 0; j < 8; ++j) { s[j][0] = s[j][1] = s[j][2] = s[j][3] = 0.f; }
#pragma unroll
        for (int ks = 0; ks < 4; ++ks) {
            uint32_t bh[8][2], bl[8][2];
#pragma unroll
            for (int kb = 0; kb < 4; ++kb) {
                const uint32_t ro = (uint32_t)((kb * 16 * AP + ks * 16) * 2);
                uint32_t t[4];
                ldsmB(t, Kh_u + ro, AP * 2);
                bh[kb * 2][0] = t[0]; bh[kb * 2][1] = t[1];
                bh[kb * 2 + 1][0] = t[2]; bh[kb * 2 + 1][1] = t[3];
                ldsmB(t, Kl_u + ro, AP * 2);
                bl[kb * 2][0] = t[0]; bl[kb * 2][1] = t[1];
                bl[kb * 2 + 1][0] = t[2]; bl[kb * 2 + 1][1] = t[3];
            }
            // j-interleaved; per-acc op order unchanged
#pragma unroll
            for (int j = 0; j < 8; ++j) mma16(s[j], qh[ks], bh[j]);
#pragma unroll
            for (int j = 0; j < 8; ++j) mma16(s[j], qh[ks], bl[j]);
#pragma unroll
            for (int j = 0; j < 8; ++j) mma16(s[j], ql[ks], bh[j]);
        }

        // Online softmax
        float rm0 = -1e30f, rm1 = -1e30f;
#pragma unroll
        for (int j = 0; j < 8; ++j) {
            rm0 = fmaxf(rm0, fmaxf(s[j][0], s[j][1]));
            rm1 = fmaxf(rm1, fmaxf(s[j][2], s[j][3]));
        }
        rm0 = fmaxf(rm0, __shfl_xor_sync(~0u, rm0, 1));
        rm0 = fmaxf(rm0, __shfl_xor_sync(~0u, rm0, 2));
        rm1 = fmaxf(rm1, __shfl_xor_sync(~0u, rm1, 1));
        rm1 = fmaxf(rm1, __shfl_xor_sync(~0u, rm1, 2));
        const float mn0 = fmaxf(m0, rm0), mn1 = fmaxf(m1, rm1);
        const float a0 = __expf(m0 - mn0), a1 = __expf(m1 - mn1);
        m0 = mn0; m1 = mn1;

        uint32_t pah[4][4], pal[4][4];
        float rs0 = 0.f, rs1 = 0.f;
#pragma unroll
        for (int j = 0; j < 8; ++j) {
            const float p0 = __expf(s[j][0] - mn0);
            const float p1 = __expf(s[j][1] - mn0);
            const float p2 = __expf(s[j][2] - mn1);
            const float p3 = __expf(s[j][3] - mn1);
            rs0 += p0 + p1; rs1 += p2 + p3;
            uint32_t h01, l01, h23, l23;
            split_pack(p0, p1, h01, l01);
            split_pack(p2, p3, h23, l23);
            const int ks = j >> 1, hf = (j & 1) * 2;
            pah[ks][hf] = h01; pah[ks][hf + 1] = h23;
            pal[ks][hf] = l01; pal[ks][hf + 1] = l23;
        }
        rs0 += __shfl_xor_sync(~0u, rs0, 1);
        rs0 += __shfl_xor_sync(~0u, rs0, 2);
        rs1 += __shfl_xor_sync(~0u, rs1, 1);
        rs1 += __shfl_xor_sync(~0u, rs1, 2);
        l0 = l0 * a0 + rs0;
        l1 = l1 * a1 + rs1;
#pragma unroll
        for (int j = 0; j < 8; ++j) {
            O[j][0] *= a0; O[j][1] *= a0; O[j][2] *= a1; O[j][3] *= a1;
        }

        // O += P @ V
#pragma unroll
        for (int ks = 0; ks < 4; ++ks) {
            uint32_t vh[8][2], vl[8][2];
#pragma unroll
            for (int db = 0; db < 4; ++db) {
                const uint32_t ro = (uint32_t)((ks * 16 * AP + db * 16) * 2);
                uint32_t t[4];
                ldsmAT(t, Vh_u + ro, AP * 2);
                vh[db * 2][0] = t[0]; vh[db * 2][1] = t[1];
                vh[db * 2 + 1][0] = t[2]; vh[db * 2 + 1][1] = t[3];
                ldsmAT(t, Vl_u + ro, AP * 2);
                vl[db * 2][0] = t[0]; vl[db * 2][1] = t[1];
                vl[db * 2 + 1][0] = t[2]; vl[db * 2 + 1][1] = t[3];
            }
#pragma unroll
            for (int j = 0; j < 8; ++j) mma16(O[j], pah[ks], vh[j]);
#pragma unroll
            for (int j = 0; j < 8; ++j) mma16(O[j], pah[ks], vl[j]);
#pragma unroll
            for (int j = 0; j < 8; ++j) mma16(O[j], pal[ks], vh[j]);
        }
    }

    // Epilogue: normalize, split to hi/lo planes for GEMM2
    const float i0 = 1.f / l0, i1 = 1.f / l1;
    const size_t r0 = ((size_t)b * NSEQ + (size_t)qt * 128 + w16 + gid) * DIMM + h * DHEAD;
    const size_t r1 = r0 + 8 * DIMM;
#pragma unroll
    for (int j = 0; j < 8; ++j) {
        const int col = j * 8 + tig * 2;
        uint32_t h0, l0u, h1, l1u;
        split_pack(O[j][0] * i0, O[j][1] * i0, h0, l0u);
        split_pack(O[j][2] * i1, O[j][3] * i1, h1, l1u);
        *(uint32_t*)(aoh + r0 + col) = h0;
        *(uint32_t*)(aol + r0 + col) = l0u;
        *(uint32_t*)(aoh + r1 + col) = h1;
        *(uint32_t*)(aol + r1 + col) = l1u;
    }
}

// ---------------------------------------------------------------------------
extern "C" void kernel_launch(void* const* d_in, const int* in_sizes, int n_in,
                              void* d_out, int out_size)
{
    const float* x     = (const float*)d_in[0];
    const float* w_qkv = (const float*)d_in[1];
    const float* w_out = (const float*)d_in[2];
    const float* b_out = (const float*)d_in[3];
    float* out = (float*)d_out;

    __nv_bfloat16 *xh, *xl, *qh, *qlp, *aoh, *aol, *wqh, *wql, *woh, *wol;
    cudaGetSymbolAddress((void**)&xh, g_xh);
    cudaGetSymbolAddress((void**)&xl, g_xl);
    cudaGetSymbolAddress((void**)&qh, g_qkvh);
    cudaGetSymbolAddress((void**)&qlp, g_qkvl);
    cudaGetSymbolAddress((void**)&aoh, g_aoh);
    cudaGetSymbolAddress((void**)&aol, g_aol);
    cudaGetSymbolAddress((void**)&wqh, g_wqkvT_hi);
    cudaGetSymbolAddress((void**)&wql, g_wqkvT_lo);
    cudaGetSymbolAddress((void**)&woh, g_woutT_hi);
    cudaGetSymbolAddress((void**)&wol, g_woutT_lo);

    const int M = NB * NSEQ;   // 8192

    // 0) split x; transpose+split weights
    const int n2 = M * DIMM / 2;
    split_f32<<<(n2 + 255) / 256, 256>>>(x, xh, xl, n2);
    transpose_split<<<dim3(QKVC / 32, DIMM / 32), dim3(32, 8)>>>(w_qkv, wqh, wql, DIMM, QKVC);
    transpose_split<<<dim3(DIMM / 32, DIMM / 32), dim3(32, 8)>>>(w_out, woh, wol, DIMM, DIMM);

    // 1) QKV projection -> split planes (q third pre-scaled 1/8)
    const int gsmem = 2 * GBUF * (int)sizeof(__nv_bfloat16);   // 81920 -> 2 CTAs/SM
    cudaFuncSetAttribute(gemm_cp<true>,  cudaFuncAttributeMaxDynamicSharedMemorySize, gsmem);
    cudaFuncSetAttribute(gemm_cp<false>, cudaFuncAttributeMaxDynamicSharedMemorySize, gsmem);
    gemm_cp<true><<<dim3(QKVC / 128, M / 128), 256, gsmem>>>(
        xh, xl, wqh, wql, nullptr, nullptr, qh, qlp, M, QKVC, DIMM);

    // 2) Flash attention
    const int asmem = (2 * APLANE_Q + 4 * KVBUF) * (int)sizeof(__nv_bfloat16);   // 184320
    cudaFuncSetAttribute(attn_cp, cudaFuncAttributeMaxDynamicSharedMemorySize, asmem);
    attn_cp<<<dim3(NSEQ / 128, NH, NB), 256, asmem>>>(qh, qlp, aoh, aol);

    // 3) Output projection + bias -> fp32
    gemm_cp<false><<<dim3(DIMM / 128, M / 128), 256, gsmem>>>(
        aoh, aol, woh, wol, b_out, out, nullptr, nullptr, M, DIMM, DIMM);
}

// round 15
// speedup vs baseline: 1.0599x; 1.0599x over previous
#include <cuda_runtime.h>
#include <cuda_bf16.h>
#include <cstdint>
#include <cstddef>

// ---------------------------------------------------------------------------
// Problem constants
// ---------------------------------------------------------------------------
#define NB    4
#define NSEQ  2048
#define DIMM  512
#define NH    8
#define DHEAD 64
#define QKVC  1536   // 3 * inner

// q third pre-scale: (1/sqrt(64)) * log2(e)  -> softmax runs in base-2 domain
#define QSCALE 0.18033688011112042f

// Scratch: all intermediates live as bf16 hi/lo residual planes.
__device__ __nv_bfloat16 g_xh [(size_t)NB * NSEQ * DIMM];
__device__ __nv_bfloat16 g_xl [(size_t)NB * NSEQ * DIMM];
__device__ __nv_bfloat16 g_qkvh[(size_t)NB * NSEQ * QKVC];
__device__ __nv_bfloat16 g_qkvl[(size_t)NB * NSEQ * QKVC];
__device__ __nv_bfloat16 g_aoh[(size_t)NB * NSEQ * DIMM];
__device__ __nv_bfloat16 g_aol[(size_t)NB * NSEQ * DIMM];
__device__ __nv_bfloat16 g_wqkvT_hi[(size_t)QKVC * DIMM];
__device__ __nv_bfloat16 g_wqkvT_lo[(size_t)QKVC * DIMM];
__device__ __nv_bfloat16 g_woutT_hi[(size_t)DIMM * DIMM];
__device__ __nv_bfloat16 g_woutT_lo[(size_t)DIMM * DIMM];

// ---------------------------------------------------------------------------
// Helpers
// ---------------------------------------------------------------------------
__device__ __forceinline__ void split_pack(float a, float b, uint32_t& hi, uint32_t& lo) {
    __nv_bfloat162 h = __floats2bfloat162_rn(a, b);
    float ra = a - __bfloat162float(h.x);
    float rb = b - __bfloat162float(h.y);
    __nv_bfloat162 l = __floats2bfloat162_rn(ra, rb);
    hi = reinterpret_cast<uint32_t&>(h);
    lo = reinterpret_cast<uint32_t&>(l);
}

__device__ __forceinline__ float ex2f(float x) {
    float r;
    asm("ex2.approx.f32 %0, %1;" : "=f"(r) : "f"(x));
    return r;
}

__device__ __forceinline__ void mma16(float* c, const uint32_t* a, const uint32_t* b) {
    asm volatile(
        "mma.sync.aligned.m16n8k16.row.col.f32.bf16.bf16.f32 "
        "{%0,%1,%2,%3}, {%4,%5,%6,%7}, {%8,%9}, {%0,%1,%2,%3};\n"
        : "+f"(c[0]), "+f"(c[1]), "+f"(c[2]), "+f"(c[3])
        : "r"(a[0]), "r"(a[1]), "r"(a[2]), "r"(a[3]), "r"(b[0]), "r"(b[1]));
}

// ldmatrix x4, A-style tile order
__device__ __forceinline__ void ldsmA(uint32_t* f, uint32_t base, int strideB) {
    const int lane = threadIdx.x & 31;
    uint32_t a = base + (uint32_t)((((lane >> 3) & 1) * 8 + (lane & 7)) * strideB + (lane >> 4) * 16);
    asm volatile("ldmatrix.sync.aligned.m8n8.x4.shared.b16 {%0,%1,%2,%3}, [%4];"
                 : "=r"(f[0]), "=r"(f[1]), "=r"(f[2]), "=r"(f[3]) : "r"(a));
}
__device__ __forceinline__ void ldsmAT(uint32_t* f, uint32_t base, int strideB) {
    const int lane = threadIdx.x & 31;
    uint32_t a = base + (uint32_t)((((lane >> 3) & 1) * 8 + (lane & 7)) * strideB + (lane >> 4) * 16);
    asm volatile("ldmatrix.sync.aligned.m8n8.x4.trans.shared.b16 {%0,%1,%2,%3}, [%4];"
                 : "=r"(f[0]), "=r"(f[1]), "=r"(f[2]), "=r"(f[3]) : "r"(a));
}
__device__ __forceinline__ void ldsmB(uint32_t* f, uint32_t base, int strideB) {
    const int lane = threadIdx.x & 31;
    uint32_t a = base + (uint32_t)(((lane >> 4) * 8 + (lane & 7)) * strideB + ((lane >> 3) & 1) * 16);
    asm volatile("ldmatrix.sync.aligned.m8n8.x4.shared.b16 {%0,%1,%2,%3}, [%4];"
                 : "=r"(f[0]), "=r"(f[1]), "=r"(f[2]), "=r"(f[3]) : "r"(a));
}

// cp.async 16B
__device__ __forceinline__ void cpa16(uint32_t dst, const void* src) {
    asm volatile("cp.async.cg.shared.global [%0], [%1], 16;" :: "r"(dst), "l"(src));
}
#define CPA_COMMIT() asm volatile("cp.async.commit_group;" ::: "memory")
#define CPA_WAIT0()  asm volatile("cp.async.wait_group 0;" ::: "memory")
#define CPA_WAIT1()  asm volatile("cp.async.wait_group 1;" ::: "memory")

// ---------------------------------------------------------------------------
// Pre-passes
// ---------------------------------------------------------------------------
__global__ void split_f32(const float* __restrict__ in,
                          __nv_bfloat16* __restrict__ oh,
                          __nv_bfloat16* __restrict__ ol, int n2)
{
    int i = blockIdx.x * blockDim.x + threadIdx.x;
    if (i < n2) {
        float2 v = ((const float2*)in)[i];
        uint32_t h, l;
        split_pack(v.x, v.y, h, l);
        ((uint32_t*)oh)[i] = h;
        ((uint32_t*)ol)[i] = l;
    }
}

__global__ void transpose_split(const float* __restrict__ W,
                                __nv_bfloat16* __restrict__ Thi,
                                __nv_bfloat16* __restrict__ Tlo, int K, int N)
{
    __shared__ float t[32][33];
    const int n0 = blockIdx.x * 32, k0 = blockIdx.y * 32;
    const int tx = threadIdx.x, ty = threadIdx.y;
#pragma unroll
    for (int j = ty; j < 32; j += 8)
        t[j][tx] = W[(size_t)(k0 + j) * N + n0 + tx];
    __syncthreads();
#pragma unroll
    for (int j = ty; j < 32; j += 8) {
        float v = t[tx][j];
        __nv_bfloat16 h = __float2bfloat16(v);
        Thi[(size_t)(n0 + j) * K + k0 + tx] = h;
        Tlo[(size_t)(n0 + j) * K + k0 + tx] = __float2bfloat16(v - __bfloat162float(h));
    }
}

// ---------------------------------------------------------------------------
// bf16x3 GEMM: 2-stage ring, 80KB smem, <=128 regs -> 2 CTAs/SM.
// (round-14 structure, unchanged except q-third scale constant)
// ---------------------------------------------------------------------------
#define GP 40
#define GPLANE (128 * GP)
#define GBUF (4 * GPLANE)

template <bool SPLITOUT>
__global__ __launch_bounds__(256, 2)
void gemm_cp(const __nv_bfloat16* __restrict__ Ah, const __nv_bfloat16* __restrict__ Al,
             const __nv_bfloat16* __restrict__ Bh, const __nv_bfloat16* __restrict__ Bl,
             const float* __restrict__ bias, float* __restrict__ Cf,
             __nv_bfloat16* __restrict__ Ch, __nv_bfloat16* __restrict__ Cl,
             int M, int N, int K)
{
    extern __shared__ __nv_bfloat16 smg[];
    const int tid = threadIdx.x;
    const int wid = tid >> 5, lane = tid & 31;
    const int gid = lane >> 2, tig = lane & 3;
    const int wm = wid >> 2, wn = wid & 3;
    const int m0 = blockIdx.y * 128, n0 = blockIdx.x * 128;
    const int NC = K >> 5;

    const uint32_t smg_u = (uint32_t)__cvta_generic_to_shared(smg);

    auto issue = [&](int c, int bb) {
        const uint32_t dbase = smg_u + (uint32_t)(bb * GBUF) * 2;
        const int kc = c * 32;
#pragma unroll
        for (int k = 0; k < 8; ++k) {
            const int i = tid + k * 256;
            const int plane = i >> 9;
            const int row = (i & 511) >> 2;
            const int ch = i & 3;
            const __nv_bfloat16* sp =
                plane == 0 ? (Ah + (size_t)(m0 + row) * K) :
                plane == 1 ? (Al + (size_t)(m0 + row) * K) :
                plane == 2 ? (Bh + (size_t)(n0 + row) * K) :
                             (Bl + (size_t)(n0 + row) * K);
            const uint32_t dst = dbase + (uint32_t)(plane * GPLANE * 2 + row * GP * 2 + ch * 16);
            cpa16(dst, sp + kc + ch * 8);
        }
        CPA_COMMIT();
    };

    float acc[4][4][4] = {};

    issue(0, 0);
    CPA_WAIT0();
    __syncthreads();

    for (int c = 0; c < NC; ++c) {
        if (c + 1 < NC) issue(c + 1, (c + 1) & 1);
        const uint32_t bu = smg_u + (uint32_t)((c & 1) * GBUF) * 2;
        const uint32_t Ahi_u = bu, Alo_u = bu + GPLANE * 2;
        const uint32_t Bhi_u = bu + 2 * GPLANE * 2, Blo_u = bu + 3 * GPLANE * 2;
#pragma unroll
        for (int ks = 0; ks < 2; ++ks) {
            uint32_t bh2[4][2], bl2[4][2];
#pragma unroll
            for (int nb = 0; nb < 2; ++nb) {
                const uint32_t ro = (uint32_t)(((wn * 32 + nb * 16) * GP + ks * 16) * 2);
                uint32_t t[4];
                ldsmB(t, Bhi_u + ro, GP * 2);
                bh2[nb * 2][0] = t[0]; bh2[nb * 2][1] = t[1];
                bh2[nb * 2 + 1][0] = t[2]; bh2[nb * 2 + 1][1] = t[3];
                ldsmB(t, Blo_u + ro, GP * 2);
                bl2[nb * 2][0] = t[0]; bl2[nb * 2][1] = t[1];
                bl2[nb * 2 + 1][0] = t[2]; bl2[nb * 2 + 1][1] = t[3];
            }
            uint32_t ah[2][4], al[2][4];
            {
                const uint32_t ro = (uint32_t)(((wm * 64) * GP + ks * 16) * 2);
                ldsmA(ah[0], Ahi_u + ro, GP * 2);
                ldsmA(al[0], Alo_u + ro, GP * 2);
            }
#pragma unroll
            for (int i = 0; i < 4; ++i) {
                const int cur = i & 1, nxt = cur ^ 1;
                if (i < 3) {
                    const uint32_t ro = (uint32_t)(((wm * 64 + (i + 1) * 16) * GP + ks * 16) * 2);
                    ldsmA(ah[nxt], Ahi_u + ro, GP * 2);
                    ldsmA(al[nxt], Alo_u + ro, GP * 2);
                }
#pragma unroll
                for (int j = 0; j < 4; ++j) mma16(acc[i][j], ah[cur], bh2[j]);
#pragma unroll
                for (int j = 0; j < 4; ++j) mma16(acc[i][j], ah[cur], bl2[j]);
#pragma unroll
                for (int j = 0; j < 4; ++j) mma16(acc[i][j], al[cur], bh2[j]);
            }
        }
        if (c + 1 < NC) { CPA_WAIT0(); __syncthreads(); }
    }

    const float qs = (SPLITOUT && n0 < DIMM) ? QSCALE : 1.0f;
#pragma unroll
    for (int i = 0; i < 4; ++i) {
        const int r0 = m0 + wm * 64 + i * 16 + gid;
#pragma unroll
        for (int j = 0; j < 4; ++j) {
            const int col = n0 + wn * 32 + j * 8 + tig * 2;
            if (SPLITOUT) {
                uint32_t h, l;
                split_pack(acc[i][j][0] * qs, acc[i][j][1] * qs, h, l);
                *(uint32_t*)(Ch + (size_t)r0 * N + col) = h;
                *(uint32_t*)(Cl + (size_t)r0 * N + col) = l;
                split_pack(acc[i][j][2] * qs, acc[i][j][3] * qs, h, l);
                *(uint32_t*)(Ch + (size_t)(r0 + 8) * N + col) = h;
                *(uint32_t*)(Cl + (size_t)(r0 + 8) * N + col) = l;
            } else {
                const float bx = bias[col], by = bias[col + 1];
                *(float2*)(Cf + (size_t)r0 * N + col) = make_float2(acc[i][j][0] + bx, acc[i][j][1] + by);
                *(float2*)(Cf + (size_t)(r0 + 8) * N + col) = make_float2(acc[i][j][2] + bx, acc[i][j][3] + by);
            }
        }
    }
}

// ---------------------------------------------------------------------------
// Flash attention: bf16x3, 2-stage cp.async KV ring, 110.6KB smem, <=128 regs
// -> 2 CTAs/SM. P frags live in the S accumulator storage (union). Softmax in
// base-2 domain (scale folded into Q by GEMM1).
// ---------------------------------------------------------------------------
#define AP 72
#define APLANE_Q (128 * AP)
#define APLANE_K (64 * AP)
#define KVBUF (4 * APLANE_K)

__global__ __launch_bounds__(256, 2)
void attn_cp(const __nv_bfloat16* __restrict__ qh_g, const __nv_bfloat16* __restrict__ ql_g,
             __nv_bfloat16* __restrict__ aoh, __nv_bfloat16* __restrict__ aol)
{
    extern __shared__ __nv_bfloat16 smb[];
    __nv_bfloat16* QPh = smb;
    __nv_bfloat16* QPl = QPh + APLANE_Q;
    __nv_bfloat16* KV  = QPl + APLANE_Q;    // [2][4 planes][64][AP]

    const uint32_t QPh_u = (uint32_t)__cvta_generic_to_shared(QPh);
    const uint32_t QPl_u = (uint32_t)__cvta_generic_to_shared(QPl);
    const uint32_t KV_u  = (uint32_t)__cvta_generic_to_shared(KV);

    const int qt = blockIdx.x, h = blockIdx.y, b = blockIdx.z;
    const int tid = threadIdx.x;
    const int wid = tid >> 5, lane = tid & 31;
    const int gid = lane >> 2, tig = lane & 3;
    const int w16 = wid * 16;

    auto issueQ = [&] {
        const size_t qbase = ((size_t)b * NSEQ + (size_t)qt * 128) * QKVC + h * DHEAD;
#pragma unroll
        for (int k = 0; k < 8; ++k) {
            const int i = tid + k * 256;
            const int plane = i >> 10;
            const int row = (i & 1023) >> 3;
            const int ch = i & 7;
            const __nv_bfloat16* src = (plane ? ql_g : qh_g) + qbase + (size_t)row * QKVC + ch * 8;
            const uint32_t dst = (plane ? QPl_u : QPh_u) + (uint32_t)(row * AP * 2 + ch * 16);
            cpa16(dst, src);
        }
        CPA_COMMIT();
    };
    auto issueKV = [&](int jt, int bb) {
        const size_t kbase = ((size_t)b * NSEQ + (size_t)jt * 64) * QKVC + h * DHEAD;
        const uint32_t dbase = KV_u + (uint32_t)(bb * KVBUF) * 2;
#pragma unroll
        for (int k = 0; k < 8; ++k) {
            const int i = tid + k * 256;
            const int plane = i >> 9;
            const int row = (i & 511) >> 3;
            const int ch = i & 7;
            const __nv_bfloat16* sp =
                plane == 0 ? (qh_g + kbase + DIMM) :
                plane == 1 ? (ql_g + kbase + DIMM) :
                plane == 2 ? (qh_g + kbase + 2 * DIMM) :
                             (ql_g + kbase + 2 * DIMM);
            const uint32_t dst = dbase + (uint32_t)(plane * APLANE_K * 2 + row * AP * 2 + ch * 16);
            cpa16(dst, sp + (size_t)row * QKVC + ch * 8);
        }
        CPA_COMMIT();
    };

    issueQ();            // group: Q
    issueKV(0, 0);       // group: KV0
    issueKV(1, 1);       // group: KV1

    uint32_t qh[4][4];   // hi Q frags resident; lo Q frags reloaded per tile
    float m0 = -1e30f, m1 = -1e30f, l0 = 0.f, l1 = 0.f;
    float O[8][4] = {};

    const int NT = NSEQ / 64;
    for (int jt = 0; jt < NT; ++jt) {
        CPA_WAIT1();         // Q+KV(jt) complete (<=1 younger group outstanding)
        __syncthreads();
        if (jt == 0) {
#pragma unroll
            for (int ks = 0; ks < 4; ++ks)
                ldsmA(qh[ks], QPh_u + (uint32_t)((w16 * AP + ks * 16) * 2), AP * 2);
        }

        const uint32_t bu = KV_u + (uint32_t)((jt & 1) * KVBUF) * 2;
        const uint32_t Kh_u = bu, Kl_u = bu + APLANE_K * 2;
        const uint32_t Vh_u = bu + 2 * APLANE_K * 2, Vl_u = bu + 3 * APLANE_K * 2;

        // S accumulators; later reused as P fragment storage.
        union SU { float f[8][4]; uint32_t u[8][4]; } su;
#pragma unroll
        for (int j = 0; j < 8; ++j) { su.f[j][0] = su.f[j][1] = su.f[j][2] = su.f[j][3] = 0.f; }

        // S = Q @ K^T (log2-domain scale folded into Q)
#pragma unroll
        for (int ks = 0; ks < 4; ++ks) {
            uint32_t ql_t[4];
            ldsmA(ql_t, QPl_u + (uint32_t)((w16 * AP + ks * 16) * 2), AP * 2);
#pragma unroll
            for (int kb = 0; kb < 4; ++kb) {
                uint32_t th[4], tl[4];
                const uint32_t ro = (uint32_t)((kb * 16 * AP + ks * 16) * 2);
                ldsmB(th, Kh_u + ro, AP * 2);
                ldsmB(tl, Kl_u + ro, AP * 2);
                mma16(su.f[2 * kb],     qh[ks], &th[0]);
                mma16(su.f[2 * kb + 1], qh[ks], &th[2]);
                mma16(su.f[2 * kb],     qh[ks], &tl[0]);
                mma16(su.f[2 * kb + 1], qh[ks], &tl[2]);
                mma16(su.f[2 * kb],     ql_t,   &th[0]);
                mma16(su.f[2 * kb + 1], ql_t,   &th[2]);
            }
        }

        // Online softmax (base 2)
        float rm0 = -1e30f, rm1 = -1e30f;
#pragma unroll
        for (int j = 0; j < 8; ++j) {
            rm0 = fmaxf(rm0, fmaxf(su.f[j][0], su.f[j][1]));
            rm1 = fmaxf(rm1, fmaxf(su.f[j][2], su.f[j][3]));
        }
        rm0 = fmaxf(rm0, __shfl_xor_sync(~0u, rm0, 1));
        rm0 = fmaxf(rm0, __shfl_xor_sync(~0u, rm0, 2));
        rm1 = fmaxf(rm1, __shfl_xor_sync(~0u, rm1, 1));
        rm1 = fmaxf(rm1, __shfl_xor_sync(~0u, rm1, 2));
        const float mn0 = fmaxf(m0, rm0), mn1 = fmaxf(m1, rm1);
        const float a0 = ex2f(m0 - mn0), a1 = ex2f(m1 - mn1);
        m0 = mn0; m1 = mn1;

        float rs0 = 0.f, rs1 = 0.f;
#pragma unroll
        for (int ks = 0; ks < 4; ++ks) {
            const float p0 = ex2f(su.f[2 * ks][0] - mn0);
            const float p1 = ex2f(su.f[2 * ks][1] - mn0);
            const float p2 = ex2f(su.f[2 * ks][2] - mn1);
            const float p3 = ex2f(su.f[2 * ks][3] - mn1);
            const float q0 = ex2f(su.f[2 * ks + 1][0] - mn0);
            const float q1 = ex2f(su.f[2 * ks + 1][1] - mn0);
            const float q2 = ex2f(su.f[2 * ks + 1][2] - mn1);
            const float q3 = ex2f(su.f[2 * ks + 1][3] - mn1);
            rs0 += p0 + p1 + q0 + q1;
            rs1 += p2 + p3 + q2 + q3;
            uint32_t h01a, l01a, h23a, l23a, h01b, l01b, h23b, l23b;
            split_pack(p0, p1, h01a, l01a);
            split_pack(p2, p3, h23a, l23a);
            split_pack(q0, q1, h01b, l01b);
            split_pack(q2, q3, h23b, l23b);
            // P-hi frag -> su.u[2ks], P-lo frag -> su.u[2ks+1]
            su.u[2 * ks][0] = h01a; su.u[2 * ks][1] = h23a;
            su.u[2 * ks][2] = h01b; su.u[2 * ks][3] = h23b;
            su.u[2 * ks + 1][0] = l01a; su.u[2 * ks + 1][1] = l23a;
            su.u[2 * ks + 1][2] = l01b; su.u[2 * ks + 1][3] = l23b;
        }
        rs0 += __shfl_xor_sync(~0u, rs0, 1);
        rs0 += __shfl_xor_sync(~0u, rs0, 2);
        rs1 += __shfl_xor_sync(~0u, rs1, 1);
        rs1 += __shfl_xor_sync(~0u, rs1, 2);
        l0 = l0 * a0 + rs0;
        l1 = l1 * a1 + rs1;
#pragma unroll
        for (int j = 0; j < 8; ++j) {
            O[j][0] *= a0; O[j][1] *= a0; O[j][2] *= a1; O[j][3] *= a1;
        }

        // O += P @ V (V^T frags via ldmatrix.trans; P frags from su.u)
#pragma unroll
        for (int ks = 0; ks < 4; ++ks) {
#pragma unroll
            for (int db = 0; db < 4; ++db) {
                uint32_t vh_t[4], vl_t[4];
                const uint32_t ro = (uint32_t)((ks * 16 * AP + db * 16) * 2);
                ldsmAT(vh_t, Vh_u + ro, AP * 2);
                ldsmAT(vl_t, Vl_u + ro, AP * 2);
                mma16(O[2 * db],     &su.u[2 * ks][0],     &vh_t[0]);
                mma16(O[2 * db + 1], &su.u[2 * ks][0],     &vh_t[2]);
                mma16(O[2 * db],     &su.u[2 * ks][0],     &vl_t[0]);
                mma16(O[2 * db + 1], &su.u[2 * ks][0],     &vl_t[2]);
                mma16(O[2 * db],     &su.u[2 * ks + 1][0], &vh_t[0]);
                mma16(O[2 * db + 1], &su.u[2 * ks + 1][0], &vh_t[2]);
            }
        }

        __syncthreads();   // all warps done reading buf jt&1
        if (jt + 2 < NT) issueKV(jt + 2, jt & 1);
    }

    // Epilogue: normalize, split to hi/lo planes for GEMM2
    const float i0 = 1.f / l0, i1 = 1.f / l1;
    const size_t r0 = ((size_t)b * NSEQ + (size_t)qt * 128 + w16 + gid) * DIMM + h * DHEAD;
    const size_t r1 = r0 + 8 * DIMM;
#pragma unroll
    for (int j = 0; j < 8; ++j) {
        const int col = j * 8 + tig * 2;
        uint32_t h0, l0u, h1, l1u;
        split_pack(O[j][0] * i0, O[j][1] * i0, h0, l0u);
        split_pack(O[j][2] * i1, O[j][3] * i1, h1, l1u);
        *(uint32_t*)(aoh + r0 + col) = h0;
        *(uint32_t*)(aol + r0 + col) = l0u;
        *(uint32_t*)(aoh + r1 + col) = h1;
        *(uint32_t*)(aol + r1 + col) = l1u;
    }
}

// ---------------------------------------------------------------------------
extern "C" void kernel_launch(void* const* d_in, const int* in_sizes, int n_in,
                              void* d_out, int out_size)
{
    const float* x     = (const float*)d_in[0];
    const float* w_qkv = (const float*)d_in[1];
    const float* w_out = (const float*)d_in[2];
    const float* b_out = (const float*)d_in[3];
    float* out = (float*)d_out;

    __nv_bfloat16 *xh, *xl, *qh, *qlp, *aoh, *aol, *wqh, *wql, *woh, *wol;
    cudaGetSymbolAddress((void**)&xh, g_xh);
    cudaGetSymbolAddress((void**)&xl, g_xl);
    cudaGetSymbolAddress((void**)&qh, g_qkvh);
    cudaGetSymbolAddress((void**)&qlp, g_qkvl);
    cudaGetSymbolAddress((void**)&aoh, g_aoh);
    cudaGetSymbolAddress((void**)&aol, g_aol);
    cudaGetSymbolAddress((void**)&wqh, g_wqkvT_hi);
    cudaGetSymbolAddress((void**)&wql, g_wqkvT_lo);
    cudaGetSymbolAddress((void**)&woh, g_woutT_hi);
    cudaGetSymbolAddress((void**)&wol, g_woutT_lo);

    const int M = NB * NSEQ;   // 8192

    // 0) split x; transpose+split weights
    const int n2 = M * DIMM / 2;
    split_f32<<<(n2 + 255) / 256, 256>>>(x, xh, xl, n2);
    transpose_split<<<dim3(QKVC / 32, DIMM / 32), dim3(32, 8)>>>(w_qkv, wqh, wql, DIMM, QKVC);
    transpose_split<<<dim3(DIMM / 32, DIMM / 32), dim3(32, 8)>>>(w_out, woh, wol, DIMM, DIMM);

    // 1) QKV projection -> split planes (q third pre-scaled by log2e/8)
    const int gsmem = 2 * GBUF * (int)sizeof(__nv_bfloat16);   // 81920 -> 2 CTAs/SM
    cudaFuncSetAttribute(gemm_cp<true>,  cudaFuncAttributeMaxDynamicSharedMemorySize, gsmem);
    cudaFuncSetAttribute(gemm_cp<false>, cudaFuncAttributeMaxDynamicSharedMemorySize, gsmem);
    gemm_cp<true><<<dim3(QKVC / 128, M / 128), 256, gsmem>>>(
        xh, xl, wqh, wql, nullptr, nullptr, qh, qlp, M, QKVC, DIMM);

    // 2) Flash attention: 110.6KB smem -> 2 CTAs/SM
    const int asmem = (2 * APLANE_Q + 2 * KVBUF) * (int)sizeof(__nv_bfloat16);   // 110592
    cudaFuncSetAttribute(attn_cp, cudaFuncAttributeMaxDynamicSharedMemorySize, asmem);
    attn_cp<<<dim3(NSEQ / 128, NH, NB), 256, asmem>>>(qh, qlp, aoh, aol);

    // 3) Output projection + bias -> fp32
    gemm_cp<false><<<dim3(DIMM / 128, M / 128), 256, gsmem>>>(
        aoh, aol, woh, wol, b_out, out, nullptr, nullptr, M, DIMM, DIMM);
}

// round 17
// speedup vs baseline: 1.0769x; 1.0160x over previous
#include <cuda_runtime.h>
#include <cuda_bf16.h>
#include <cstdint>
#include <cstddef>

// ---------------------------------------------------------------------------
// Problem constants
// ---------------------------------------------------------------------------
#define NB    4
#define NSEQ  2048
#define DIMM  512
#define NH    8
#define DHEAD 64
#define QKVC  1536   // 3 * inner

// q third pre-scale: (1/sqrt(64)) * log2(e)  -> softmax runs in base-2 domain
#define QSCALE 0.18033688011112042f

// Scratch: all intermediates live as bf16 hi/lo residual planes.
__device__ __nv_bfloat16 g_xh [(size_t)NB * NSEQ * DIMM];
__device__ __nv_bfloat16 g_xl [(size_t)NB * NSEQ * DIMM];
__device__ __nv_bfloat16 g_qkvh[(size_t)NB * NSEQ * QKVC];
__device__ __nv_bfloat16 g_qkvl[(size_t)NB * NSEQ * QKVC];
__device__ __nv_bfloat16 g_aoh[(size_t)NB * NSEQ * DIMM];
__device__ __nv_bfloat16 g_aol[(size_t)NB * NSEQ * DIMM];
__device__ __nv_bfloat16 g_wqkvT_hi[(size_t)QKVC * DIMM];
__device__ __nv_bfloat16 g_wqkvT_lo[(size_t)QKVC * DIMM];
__device__ __nv_bfloat16 g_woutT_hi[(size_t)DIMM * DIMM];
__device__ __nv_bfloat16 g_woutT_lo[(size_t)DIMM * DIMM];

// ---------------------------------------------------------------------------
// Helpers
// ---------------------------------------------------------------------------
__device__ __forceinline__ void split_pack(float a, float b, uint32_t& hi, uint32_t& lo) {
    __nv_bfloat162 h = __floats2bfloat162_rn(a, b);
    float ra = a - __bfloat162float(h.x);
    float rb = b - __bfloat162float(h.y);
    __nv_bfloat162 l = __floats2bfloat162_rn(ra, rb);
    hi = reinterpret_cast<uint32_t&>(h);
    lo = reinterpret_cast<uint32_t&>(l);
}

__device__ __forceinline__ float ex2f(float x) {
    float r;
    asm("ex2.approx.f32 %0, %1;" : "=f"(r) : "f"(x));
    return r;
}

__device__ __forceinline__ void mma16(float* c, const uint32_t* a, const uint32_t* b) {
    asm volatile(
        "mma.sync.aligned.m16n8k16.row.col.f32.bf16.bf16.f32 "
        "{%0,%1,%2,%3}, {%4,%5,%6,%7}, {%8,%9}, {%0,%1,%2,%3};\n"
        : "+f"(c[0]), "+f"(c[1]), "+f"(c[2]), "+f"(c[3])
        : "r"(a[0]), "r"(a[1]), "r"(a[2]), "r"(a[3]), "r"(b[0]), "r"(b[1]));
}

// ldmatrix x4, A-style tile order
__device__ __forceinline__ void ldsmA(uint32_t* f, uint32_t base, int strideB) {
    const int lane = threadIdx.x & 31;
    uint32_t a = base + (uint32_t)((((lane >> 3) & 1) * 8 + (lane & 7)) * strideB + (lane >> 4) * 16);
    asm volatile("ldmatrix.sync.aligned.m8n8.x4.shared.b16 {%0,%1,%2,%3}, [%4];"
                 : "=r"(f[0]), "=r"(f[1]), "=r"(f[2]), "=r"(f[3]) : "r"(a));
}
__device__ __forceinline__ void ldsmAT(uint32_t* f, uint32_t base, int strideB) {
    const int lane = threadIdx.x & 31;
    uint32_t a = base + (uint32_t)((((lane >> 3) & 1) * 8 + (lane & 7)) * strideB + (lane >> 4) * 16);
    asm volatile("ldmatrix.sync.aligned.m8n8.x4.trans.shared.b16 {%0,%1,%2,%3}, [%4];"
                 : "=r"(f[0]), "=r"(f[1]), "=r"(f[2]), "=r"(f[3]) : "r"(a));
}
__device__ __forceinline__ void ldsmB(uint32_t* f, uint32_t base, int strideB) {
    const int lane = threadIdx.x & 31;
    uint32_t a = base + (uint32_t)(((lane >> 4) * 8 + (lane & 7)) * strideB + ((lane >> 3) & 1) * 16);
    asm volatile("ldmatrix.sync.aligned.m8n8.x4.shared.b16 {%0,%1,%2,%3}, [%4];"
                 : "=r"(f[0]), "=r"(f[1]), "=r"(f[2]), "=r"(f[3]) : "r"(a));
}

// cp.async 16B
__device__ __forceinline__ void cpa16(uint32_t dst, const void* src) {
    asm volatile("cp.async.cg.shared.global [%0], [%1], 16;" :: "r"(dst), "l"(src));
}
#define CPA_COMMIT() asm volatile("cp.async.commit_group;" ::: "memory")
#define CPA_WAIT0()  asm volatile("cp.async.wait_group 0;" ::: "memory")
#define CPA_WAIT1()  asm volatile("cp.async.wait_group 1;" ::: "memory")

// ---------------------------------------------------------------------------
// Pre-passes
// ---------------------------------------------------------------------------
__global__ void split_f32(const float* __restrict__ in,
                          __nv_bfloat16* __restrict__ oh,
                          __nv_bfloat16* __restrict__ ol, int n2)
{
    int i = blockIdx.x * blockDim.x + threadIdx.x;
    if (i < n2) {
        float2 v = ((const float2*)in)[i];
        uint32_t h, l;
        split_pack(v.x, v.y, h, l);
        ((uint32_t*)oh)[i] = h;
        ((uint32_t*)ol)[i] = l;
    }
}

__global__ void transpose_split(const float* __restrict__ W,
                                __nv_bfloat16* __restrict__ Thi,
                                __nv_bfloat16* __restrict__ Tlo, int K, int N)
{
    __shared__ float t[32][33];
    const int n0 = blockIdx.x * 32, k0 = blockIdx.y * 32;
    const int tx = threadIdx.x, ty = threadIdx.y;
#pragma unroll
    for (int j = ty; j < 32; j += 8)
        t[j][tx] = W[(size_t)(k0 + j) * N + n0 + tx];
    __syncthreads();
#pragma unroll
    for (int j = ty; j < 32; j += 8) {
        float v = t[tx][j];
        __nv_bfloat16 h = __float2bfloat16(v);
        Thi[(size_t)(n0 + j) * K + k0 + tx] = h;
        Tlo[(size_t)(n0 + j) * K + k0 + tx] = __float2bfloat16(v - __bfloat162float(h));
    }
}

// ---------------------------------------------------------------------------
// bf16x3 GEMM: 2-stage ring, 80KB smem, <=128 regs -> 2 CTAs/SM.
// Stream-major mma order: each accumulator is reused only after 16 other
// mmas (covers HMMA accumulate latency). Per-acc op order: hh, hl, lh.
// ---------------------------------------------------------------------------
#define GP 40
#define GPLANE (128 * GP)
#define GBUF (4 * GPLANE)

template <bool SPLITOUT>
__global__ __launch_bounds__(256, 2)
void gemm_cp(const __nv_bfloat16* __restrict__ Ah, const __nv_bfloat16* __restrict__ Al,
             const __nv_bfloat16* __restrict__ Bh, const __nv_bfloat16* __restrict__ Bl,
             const float* __restrict__ bias, float* __restrict__ Cf,
             __nv_bfloat16* __restrict__ Ch, __nv_bfloat16* __restrict__ Cl,
             int M, int N, int K)
{
    extern __shared__ __nv_bfloat16 smg[];
    const int tid = threadIdx.x;
    const int wid = tid >> 5, lane = tid & 31;
    const int gid = lane >> 2, tig = lane & 3;
    const int wm = wid >> 2, wn = wid & 3;
    const int m0 = blockIdx.y * 128, n0 = blockIdx.x * 128;
    const int NC = K >> 5;

    const uint32_t smg_u = (uint32_t)__cvta_generic_to_shared(smg);

    auto issue = [&](int c, int bb) {
        const uint32_t dbase = smg_u + (uint32_t)(bb * GBUF) * 2;
        const int kc = c * 32;
#pragma unroll
        for (int k = 0; k < 8; ++k) {
            const int i = tid + k * 256;
            const int plane = i >> 9;
            const int row = (i & 511) >> 2;
            const int ch = i & 3;
            const __nv_bfloat16* sp =
                plane == 0 ? (Ah + (size_t)(m0 + row) * K) :
                plane == 1 ? (Al + (size_t)(m0 + row) * K) :
                plane == 2 ? (Bh + (size_t)(n0 + row) * K) :
                             (Bl + (size_t)(n0 + row) * K);
            const uint32_t dst = dbase + (uint32_t)(plane * GPLANE * 2 + row * GP * 2 + ch * 16);
            cpa16(dst, sp + kc + ch * 8);
        }
        CPA_COMMIT();
    };

    float acc[4][4][4] = {};

    issue(0, 0);
    CPA_WAIT0();
    __syncthreads();

    for (int c = 0; c < NC; ++c) {
        if (c + 1 < NC) issue(c + 1, (c + 1) & 1);
        const uint32_t bu = smg_u + (uint32_t)((c & 1) * GBUF) * 2;
        const uint32_t Ahi_u = bu, Alo_u = bu + GPLANE * 2;
        const uint32_t Bhi_u = bu + 2 * GPLANE * 2, Blo_u = bu + 3 * GPLANE * 2;
#pragma unroll
        for (int ks = 0; ks < 2; ++ks) {
            // B fragments for this ks
            uint32_t bh2[4][2], bl2[4][2];
#pragma unroll
            for (int nb = 0; nb < 2; ++nb) {
                const uint32_t ro = (uint32_t)(((wn * 32 + nb * 16) * GP + ks * 16) * 2);
                uint32_t t[4];
                ldsmB(t, Bhi_u + ro, GP * 2);
                bh2[nb * 2][0] = t[0]; bh2[nb * 2][1] = t[1];
                bh2[nb * 2 + 1][0] = t[2]; bh2[nb * 2 + 1][1] = t[3];
                ldsmB(t, Blo_u + ro, GP * 2);
                bl2[nb * 2][0] = t[0]; bl2[nb * 2][1] = t[1];
                bl2[nb * 2 + 1][0] = t[2]; bl2[nb * 2 + 1][1] = t[3];
            }
            // All A fragments for this ks
            uint32_t ah[4][4], al[4][4];
#pragma unroll
            for (int i = 0; i < 4; ++i) {
                const uint32_t ro = (uint32_t)(((wm * 64 + i * 16) * GP + ks * 16) * 2);
                ldsmA(ah[i], Ahi_u + ro, GP * 2);
                ldsmA(al[i], Alo_u + ro, GP * 2);
            }
            // Stream-major: same-acc reuse distance = 16 mmas.
#pragma unroll
            for (int j = 0; j < 4; ++j)
#pragma unroll
                for (int i = 0; i < 4; ++i) mma16(acc[i][j], ah[i], bh2[j]);
#pragma unroll
            for (int j = 0; j < 4; ++j)
#pragma unroll
                for (int i = 0; i < 4; ++i) mma16(acc[i][j], ah[i], bl2[j]);
#pragma unroll
            for (int j = 0; j < 4; ++j)
#pragma unroll
                for (int i = 0; i < 4; ++i) mma16(acc[i][j], al[i], bh2[j]);
        }
        if (c + 1 < NC) { CPA_WAIT0(); __syncthreads(); }
    }

    const float qs = (SPLITOUT && n0 < DIMM) ? QSCALE : 1.0f;
#pragma unroll
    for (int i = 0; i < 4; ++i) {
        const int r0 = m0 + wm * 64 + i * 16 + gid;
#pragma unroll
        for (int j = 0; j < 4; ++j) {
            const int col = n0 + wn * 32 + j * 8 + tig * 2;
            if (SPLITOUT) {
                uint32_t h, l;
                split_pack(acc[i][j][0] * qs, acc[i][j][1] * qs, h, l);
                *(uint32_t*)(Ch + (size_t)r0 * N + col) = h;
                *(uint32_t*)(Cl + (size_t)r0 * N + col) = l;
                split_pack(acc[i][j][2] * qs, acc[i][j][3] * qs, h, l);
                *(uint32_t*)(Ch + (size_t)(r0 + 8) * N + col) = h;
                *(uint32_t*)(Cl + (size_t)(r0 + 8) * N + col) = l;
            } else {
                const float bx = bias[col], by = bias[col + 1];
                *(float2*)(Cf + (size_t)r0 * N + col) = make_float2(acc[i][j][0] + bx, acc[i][j][1] + by);
                *(float2*)(Cf + (size_t)(r0 + 8) * N + col) = make_float2(acc[i][j][2] + bx, acc[i][j][3] + by);
            }
        }
    }
}

// ---------------------------------------------------------------------------
// Flash attention: bf16x3, 2-stage cp.async KV ring, 110.6KB smem, 2 CTAs/SM.
// Stream-major mma order (same-acc gap = 8). P frags in S storage (union).
// Softmax in base-2 domain (scale folded into Q).
// ---------------------------------------------------------------------------
#define AP 72
#define APLANE_Q (128 * AP)
#define APLANE_K (64 * AP)
#define KVBUF (4 * APLANE_K)

__global__ __launch_bounds__(256, 2)
void attn_cp(const __nv_bfloat16* __restrict__ qh_g, const __nv_bfloat16* __restrict__ ql_g,
             __nv_bfloat16* __restrict__ aoh, __nv_bfloat16* __restrict__ aol)
{
    extern __shared__ __nv_bfloat16 smb[];
    __nv_bfloat16* QPh = smb;
    __nv_bfloat16* QPl = QPh + APLANE_Q;
    __nv_bfloat16* KV  = QPl + APLANE_Q;    // [2][4 planes][64][AP]

    const uint32_t QPh_u = (uint32_t)__cvta_generic_to_shared(QPh);
    const uint32_t QPl_u = (uint32_t)__cvta_generic_to_shared(QPl);
    const uint32_t KV_u  = (uint32_t)__cvta_generic_to_shared(KV);

    const int qt = blockIdx.x, h = blockIdx.y, b = blockIdx.z;
    const int tid = threadIdx.x;
    const int wid = tid >> 5, lane = tid & 31;
    const int gid = lane >> 2, tig = lane & 3;
    const int w16 = wid * 16;

    auto issueQ = [&] {
        const size_t qbase = ((size_t)b * NSEQ + (size_t)qt * 128) * QKVC + h * DHEAD;
#pragma unroll
        for (int k = 0; k < 8; ++k) {
            const int i = tid + k * 256;
            const int plane = i >> 10;
            const int row = (i & 1023) >> 3;
            const int ch = i & 7;
            const __nv_bfloat16* src = (plane ? ql_g : qh_g) + qbase + (size_t)row * QKVC + ch * 8;
            const uint32_t dst = (plane ? QPl_u : QPh_u) + (uint32_t)(row * AP * 2 + ch * 16);
            cpa16(dst, src);
        }
        CPA_COMMIT();
    };
    auto issueKV = [&](int jt, int bb) {
        const size_t kbase = ((size_t)b * NSEQ + (size_t)jt * 64) * QKVC + h * DHEAD;
        const uint32_t dbase = KV_u + (uint32_t)(bb * KVBUF) * 2;
#pragma unroll
        for (int k = 0; k < 8; ++k) {
            const int i = tid + k * 256;
            const int plane = i >> 9;
            const int row = (i & 511) >> 3;
            const int ch = i & 7;
            const __nv_bfloat16* sp =
                plane == 0 ? (qh_g + kbase + DIMM) :
                plane == 1 ? (ql_g + kbase + DIMM) :
                plane == 2 ? (qh_g + kbase + 2 * DIMM) :
                             (ql_g + kbase + 2 * DIMM);
            const uint32_t dst = dbase + (uint32_t)(plane * APLANE_K * 2 + row * AP * 2 + ch * 16);
            cpa16(dst, sp + (size_t)row * QKVC + ch * 8);
        }
        CPA_COMMIT();
    };

    issueQ();
    issueKV(0, 0);
    issueKV(1, 1);

    uint32_t qh[4][4];
    float m0 = -1e30f, m1 = -1e30f, l0 = 0.f, l1 = 0.f;
    float O[8][4] = {};

    const int NT = NSEQ / 64;
    for (int jt = 0; jt < NT; ++jt) {
        CPA_WAIT1();
        __syncthreads();
        if (jt == 0) {
#pragma unroll
            for (int ks = 0; ks < 4; ++ks)
                ldsmA(qh[ks], QPh_u + (uint32_t)((w16 * AP + ks * 16) * 2), AP * 2);
        }

        const uint32_t bu = KV_u + (uint32_t)((jt & 1) * KVBUF) * 2;
        const uint32_t Kh_u = bu, Kl_u = bu + APLANE_K * 2;
        const uint32_t Vh_u = bu + 2 * APLANE_K * 2, Vl_u = bu + 3 * APLANE_K * 2;

        union SU { float f[8][4]; uint32_t u[8][4]; } su;
#pragma unroll
        for (int j = 0; j < 8; ++j) { su.f[j][0] = su.f[j][1] = su.f[j][2] = su.f[j][3] = 0.f; }

        // S = Q @ K^T, stream-major per ks (same-acc gap = 8)
#pragma unroll
        for (int ks = 0; ks < 4; ++ks) {
            uint32_t ql_t[4];
            ldsmA(ql_t, QPl_u + (uint32_t)((w16 * AP + ks * 16) * 2), AP * 2);
            uint32_t kh[8][2], kl[8][2];
#pragma unroll
            for (int kb = 0; kb < 4; ++kb) {
                const uint32_t ro = (uint32_t)((kb * 16 * AP + ks * 16) * 2);
                uint32_t t[4];
                ldsmB(t, Kh_u + ro, AP * 2);
                kh[2 * kb][0] = t[0]; kh[2 * kb][1] = t[1];
                kh[2 * kb + 1][0] = t[2]; kh[2 * kb + 1][1] = t[3];
                ldsmB(t, Kl_u + ro, AP * 2);
                kl[2 * kb][0] = t[0]; kl[2 * kb][1] = t[1];
                kl[2 * kb + 1][0] = t[2]; kl[2 * kb + 1][1] = t[3];
            }
#pragma unroll
            for (int j = 0; j < 8; ++j) mma16(su.f[j], qh[ks], kh[j]);
#pragma unroll
            for (int j = 0; j < 8; ++j) mma16(su.f[j], qh[ks], kl[j]);
#pragma unroll
            for (int j = 0; j < 8; ++j) mma16(su.f[j], ql_t, kh[j]);
        }

        // Online softmax (base 2)
        float rm0 = -1e30f, rm1 = -1e30f;
#pragma unroll
        for (int j = 0; j < 8; ++j) {
            rm0 = fmaxf(rm0, fmaxf(su.f[j][0], su.f[j][1]));
            rm1 = fmaxf(rm1, fmaxf(su.f[j][2], su.f[j][3]));
        }
        rm0 = fmaxf(rm0, __shfl_xor_sync(~0u, rm0, 1));
        rm0 = fmaxf(rm0, __shfl_xor_sync(~0u, rm0, 2));
        rm1 = fmaxf(rm1, __shfl_xor_sync(~0u, rm1, 1));
        rm1 = fmaxf(rm1, __shfl_xor_sync(~0u, rm1, 2));
        const float mn0 = fmaxf(m0, rm0), mn1 = fmaxf(m1, rm1);
        const float a0 = ex2f(m0 - mn0), a1 = ex2f(m1 - mn1);
        m0 = mn0; m1 = mn1;

        float rs0 = 0.f, rs1 = 0.f;
#pragma unroll
        for (int ks = 0; ks < 4; ++ks) {
            const float p0 = ex2f(su.f[2 * ks][0] - mn0);
            const float p1 = ex2f(su.f[2 * ks][1] - mn0);
            const float p2 = ex2f(su.f[2 * ks][2] - mn1);
            const float p3 = ex2f(su.f[2 * ks][3] - mn1);
            const float q0 = ex2f(su.f[2 * ks + 1][0] - mn0);
            const float q1 = ex2f(su.f[2 * ks + 1][1] - mn0);
            const float q2 = ex2f(su.f[2 * ks + 1][2] - mn1);
            const float q3 = ex2f(su.f[2 * ks + 1][3] - mn1);
            rs0 += p0 + p1 + q0 + q1;
            rs1 += p2 + p3 + q2 + q3;
            uint32_t h01a, l01a, h23a, l23a, h01b, l01b, h23b, l23b;
            split_pack(p0, p1, h01a, l01a);
            split_pack(p2, p3, h23a, l23a);
            split_pack(q0, q1, h01b, l01b);
            split_pack(q2, q3, h23b, l23b);
            su.u[2 * ks][0] = h01a; su.u[2 * ks][1] = h23a;
            su.u[2 * ks][2] = h01b; su.u[2 * ks][3] = h23b;
            su.u[2 * ks + 1][0] = l01a; su.u[2 * ks + 1][1] = l23a;
            su.u[2 * ks + 1][2] = l01b; su.u[2 * ks + 1][3] = l23b;
        }
        rs0 += __shfl_xor_sync(~0u, rs0, 1);
        rs0 += __shfl_xor_sync(~0u, rs0, 2);
        rs1 += __shfl_xor_sync(~0u, rs1, 1);
        rs1 += __shfl_xor_sync(~0u, rs1, 2);
        l0 = l0 * a0 + rs0;
        l1 = l1 * a1 + rs1;
#pragma unroll
        for (int j = 0; j < 8; ++j) {
            O[j][0] *= a0; O[j][1] *= a0; O[j][2] *= a1; O[j][3] *= a1;
        }

        // O += P @ V, stream-major per ks (same-acc gap = 8)
#pragma unroll
        for (int ks = 0; ks < 4; ++ks) {
            uint32_t vh[8][2], vl[8][2];
#pragma unroll
            for (int db = 0; db < 4; ++db) {
                const uint32_t ro = (uint32_t)((ks * 16 * AP + db * 16) * 2);
                uint32_t t[4];
                ldsmAT(t, Vh_u + ro, AP * 2);
                vh[2 * db][0] = t[0]; vh[2 * db][1] = t[1];
                vh[2 * db + 1][0] = t[2]; vh[2 * db + 1][1] = t[3];
                ldsmAT(t, Vl_u + ro, AP * 2);
                vl[2 * db][0] = t[0]; vl[2 * db][1] = t[1];
                vl[2 * db + 1][0] = t[2]; vl[2 * db + 1][1] = t[3];
            }
#pragma unroll
            for (int j = 0; j < 8; ++j) mma16(O[j], &su.u[2 * ks][0], vh[j]);
#pragma unroll
            for (int j = 0; j < 8; ++j) mma16(O[j], &su.u[2 * ks][0], vl[j]);
#pragma unroll
            for (int j = 0; j < 8; ++j) mma16(O[j], &su.u[2 * ks + 1][0], vh[j]);
        }

        __syncthreads();
        if (jt + 2 < NT) issueKV(jt + 2, jt & 1);
    }

    // Epilogue: normalize, split to hi/lo planes for GEMM2
    const float i0 = 1.f / l0, i1 = 1.f / l1;
    const size_t r0 = ((size_t)b * NSEQ + (size_t)qt * 128 + w16 + gid) * DIMM + h * DHEAD;
    const size_t r1 = r0 + 8 * DIMM;
#pragma unroll
    for (int j = 0; j < 8; ++j) {
        const int col = j * 8 + tig * 2;
        uint32_t h0, l0u, h1, l1u;
        split_pack(O[j][0] * i0, O[j][1] * i0, h0, l0u);
        split_pack(O[j][2] * i1, O[j][3] * i1, h1, l1u);
        *(uint32_t*)(aoh + r0 + col) = h0;
        *(uint32_t*)(aol + r0 + col) = l0u;
        *(uint32_t*)(aoh + r1 + col) = h1;
        *(uint32_t*)(aol + r1 + col) = l1u;
    }
}

// ---------------------------------------------------------------------------
extern "C" void kernel_launch(void* const* d_in, const int* in_sizes, int n_in,
                              void* d_out, int out_size)
{
    const float* x     = (const float*)d_in[0];
    const float* w_qkv = (const float*)d_in[1];
    const float* w_out = (const float*)d_in[2];
    const float* b_out = (const float*)d_in[3];
    float* out = (float*)d_out;

    __nv_bfloat16 *xh, *xl, *qh, *qlp, *aoh, *aol, *wqh, *wql, *woh, *wol;
    cudaGetSymbolAddress((void**)&xh, g_xh);
    cudaGetSymbolAddress((void**)&xl, g_xl);
    cudaGetSymbolAddress((void**)&qh, g_qkvh);
    cudaGetSymbolAddress((void**)&qlp, g_qkvl);
    cudaGetSymbolAddress((void**)&aoh, g_aoh);
    cudaGetSymbolAddress((void**)&aol, g_aol);
    cudaGetSymbolAddress((void**)&wqh, g_wqkvT_hi);
    cudaGetSymbolAddress((void**)&wql, g_wqkvT_lo);
    cudaGetSymbolAddress((void**)&woh, g_woutT_hi);
    cudaGetSymbolAddress((void**)&wol, g_woutT_lo);

    const int M = NB * NSEQ;   // 8192

    // 0) split x; transpose+split weights
    const int n2 = M * DIMM / 2;
    split_f32<<<(n2 + 255) / 256, 256>>>(x, xh, xl, n2);
    transpose_split<<<dim3(QKVC / 32, DIMM / 32), dim3(32, 8)>>>(w_qkv, wqh, wql, DIMM, QKVC);
    transpose_split<<<dim3(DIMM / 32, DIMM / 32), dim3(32, 8)>>>(w_out, woh, wol, DIMM, DIMM);

    // 1) QKV projection -> split planes (q third pre-scaled by log2e/8)
    const int gsmem = 2 * GBUF * (int)sizeof(__nv_bfloat16);   // 81920 -> 2 CTAs/SM
    cudaFuncSetAttribute(gemm_cp<true>,  cudaFuncAttributeMaxDynamicSharedMemorySize, gsmem);
    cudaFuncSetAttribute(gemm_cp<false>, cudaFuncAttributeMaxDynamicSharedMemorySize, gsmem);
    gemm_cp<true><<<dim3(QKVC / 128, M / 128), 256, gsmem>>>(
        xh, xl, wqh, wql, nullptr, nullptr, qh, qlp, M, QKVC, DIMM);

    // 2) Flash attention: 110.6KB smem -> 2 CTAs/SM
    const int asmem = (2 * APLANE_Q + 2 * KVBUF) * (int)sizeof(__nv_bfloat16);   // 110592
    cudaFuncSetAttribute(attn_cp, cudaFuncAttributeMaxDynamicSharedMemorySize, asmem);
    attn_cp<<<dim3(NSEQ / 128, NH, NB), 256, asmem>>>(qh, qlp, aoh, aol);

    // 3) Output projection + bias -> fp32
    gemm_cp<false><<<dim3(DIMM / 128, M / 128), 256, gsmem>>>(
        aoh, aol, woh, wol, b_out, out, nullptr, nullptr, M, DIMM, DIMM);
}